// round 1
// baseline (speedup 1.0000x reference)
#include <cuda_runtime.h>
#include <math.h>

// ---------------- constants matching the reference ----------------
#define HH 121
#define WW 121
#define NE 225
#define NB 8
#define N_INTERP 200
#define RET_PER_DVA 280.0f
#define XRANGE0 (-15.0f)
#define YRANGE0 (-15.0f)
#define XYSTEP 0.25f
#define XLOWc (-4200.0f)            // XRANGE0*RET_PER_DVA
#define YLOWc (-4200.0f)
#define STEP_Xc (8400.0f/199.0f)    // (XHIGH-XLOW)/(N_INTERP-1)
#define STEP_Yc (8400.0f/199.0f)
#define OD_OFF_Xc (15.5f*280.0f)
#define AMP_CUTOFF 0.25f
#define PIc 3.14159265358979323846f
#define TEMP1c (4.0f*PIc)
#define NEG_HALF_LOG2E (-0.7213475204444817f)   // -0.5*log2(e)
#define CULL_T 44.0f                            // exp2(-44) ~ 6e-14

// scratch: compacted per-(b,e) table.  pair layout:
//   slot*2+0 : (cx, cy2, R2, bright)
//   slot*2+1 : (c00, c01, c11, 0)
__device__ float4 g_tab[NB][NE * 2];
__device__ int    g_cnt[NB];

__global__ void precompute_kernel(const float* __restrict__ stim,
                                  const float* __restrict__ params,
                                  const float* __restrict__ elec_x,
                                  const float* __restrict__ elec_y,
                                  const float* __restrict__ slopes) {
    int b = blockIdx.x;
    const float* P = params + b * 13;
    float rho = P[0], lam = P[1], osc = P[2];
    float a0 = P[3], a1 = P[4], a2 = P[5], a3 = P[6], a4 = P[7];
    float impx = P[8], impy = P[9], rot = P[10], lodx = P[11];
    float cr = cosf(rot), sr = sinf(rot);

    int e = threadIdx.x;          // blockDim = 256, 8 warps
    bool act = false;
    float cx = 0.f, cy2 = 0.f, R2 = 0.f, bright = 0.f;
    float c00 = 0.f, c01 = 0.f, c11 = 0.f;

    if (e < NE) {
        float exv = elec_x[e] * cr - elec_y[e] * sr + impx;
        float eyv = elec_x[e] * sr + elec_y[e] * cr + impy;
        float freq = stim[(b * NE + e) * 3 + 0];
        float amp  = stim[(b * NE + e) * 3 + 1];
        float pdur = stim[(b * NE + e) * 3 + 2];

        if (amp > AMP_CUTOFF) {
            act = true;
            float offx = lodx - OD_OFF_Xc;
            float qx = (exv - offx - XLOWc) / STEP_Xc;
            float qy = (eyv - YLOWc) / STEP_Yc;

            // bilinear interp on slopes (200x200), matching jnp clipping
            float fx = fminf(fmaxf(floorf(qx), 0.f), (float)(N_INTERP - 2));
            float fy = fminf(fmaxf(floorf(qy), 0.f), (float)(N_INTERP - 2));
            int ix = (int)fx, iy = (int)fy;
            float ax = fminf(fmaxf(qx - fx, 0.f), 1.f);
            float ay = fminf(fmaxf(qy - fy, 0.f), 1.f);
            float g00 = slopes[iy * N_INTERP + ix];
            float g01 = slopes[iy * N_INTERP + ix + 1];
            float g10 = slopes[(iy + 1) * N_INTERP + ix];
            float g11 = slopes[(iy + 1) * N_INTERP + ix + 1];
            float top = g00 + ax * (g01 - g00);
            float bot = g10 + ax * (g11 - g10);
            float th = top + ay * (bot - top);
            if (th < -PIc * 0.5f) th += PIc;
            th *= osc;

            float rs = fmaxf(rho * amp * a3, 1.0f);
            float ls = lam * powf(0.45f, -a4) * powf(pdur, a4);
            ls = fminf(fmaxf(ls, 0.f), 0.99f);
            bright = a0 * powf(fmaxf(amp, 1e-5f), a1) + a2 * freq;

            float t2 = sqrtf(1.0f - ls * ls);
            float sy = rs / (TEMP1c * t2);
            float sx = rs * t2 / TEMP1c;
            float s = sinf(th), c = cosf(th);
            float cov00 = sx * c * c + sy * s * s;
            float cov01 = (sx - sy) * s * c;
            float cov11 = sx * s * s + sy * c * c;
            float det = cov00 * cov11 - cov01 * cov01;
            float inv00 = cov11 / det;
            float inv01 = -cov01 / det;
            float inv11 = cov00 / det;

            // fold -0.5*log2(e); double cross term
            c00 = NEG_HALF_LOG2E * inv00;
            c01 = 2.0f * NEG_HALF_LOG2E * inv01;
            c11 = NEG_HALF_LOG2E * inv11;

            cx = (exv / RET_PER_DVA - XRANGE0) / XYSTEP;
            float cy = (float)HH - (eyv / RET_PER_DVA - YRANGE0) / XYSTEP;
            cy2 = 120.0f - cy;   // so that d1 = cy2 - r  ==  (120-r) - cy

            // culling radius: t = [d]' Q [d], Q = [[c00,c01/2],[c01/2,c11]] (neg-def)
            // lambda_min(-Q) -> |t| >= lmin*|d|^2 ; skip when lmin*|d|^2 > CULL_T
            float trn = -(c00 + c11);
            float dQ = c00 * c11 - 0.25f * c01 * c01;   // det(-Q) == det(Q) for 2x2
            float disc = fmaxf(trn * trn - 4.0f * dQ, 0.f);
            float lmin = 0.5f * (trn - sqrtf(disc));
            R2 = CULL_T / fmaxf(lmin, 1e-20f);
        }
    }

    // deterministic ballot compaction (order preserved by e)
    __shared__ int warp_cnt[8];
    unsigned mask = __ballot_sync(0xffffffffu, act);
    int lane = threadIdx.x & 31, w = threadIdx.x >> 5;
    if (lane == 0) warp_cnt[w] = __popc(mask);
    __syncthreads();
    int off = 0;
#pragma unroll
    for (int i = 0; i < 8; i++) off += (i < w) ? warp_cnt[i] : 0;
    if (threadIdx.x == 0) {
        int tot = 0;
#pragma unroll
        for (int i = 0; i < 8; i++) tot += warp_cnt[i];
        g_cnt[b] = tot;
    }
    if (act) {
        int slot = off + __popc(mask & ((1u << lane) - 1u));
        g_tab[b][slot * 2 + 0] = make_float4(cx, cy2, R2, bright);
        g_tab[b][slot * 2 + 1] = make_float4(c00, c01, c11, 0.f);
    }
}

__device__ __forceinline__ float ex2_fast(float x) {
    float r;
    asm("ex2.approx.ftz.f32 %0, %1;" : "=f"(r) : "f"(x));
    return r;
}

// main: grid (4, 16, 8), block 128.  Each warp = 32 cols x 2 rows tile,
// each thread handles 2 rows (ILP 2, shared d0).
__global__ __launch_bounds__(128) void mvg_main_kernel(float* __restrict__ out) {
    __shared__ float4 sA[NE];
    __shared__ float4 sB[NE];

    int b = blockIdx.z;
    int cnt = g_cnt[b];

    for (int i = threadIdx.x; i < cnt; i += 128) {
        sA[i] = g_tab[b][i * 2 + 0];
        sB[i] = g_tab[b][i * 2 + 1];
    }
    __syncthreads();

    int lane = threadIdx.x & 31;
    int warp = threadIdx.x >> 5;
    int c  = blockIdx.x * 32 + lane;
    int r0 = blockIdx.y * 8 + warp * 2;

    float cf  = (float)c;
    float rf0 = (float)r0;
    float rf1 = rf0 + 1.0f;

    // warp-uniform tile center (32 cols x 2 rows)
    float tcx = (float)(blockIdx.x * 32) + 15.5f;
    float tcy = rf0 + 0.5f;

    float acc0 = 0.f, acc1 = 0.f;

    for (int e = 0; e < cnt; e++) {
        float4 A = sA[e];                       // cx, cy2, R2, bright
        float dx = fmaxf(fabsf(tcx - A.x) - 15.5f, 0.f);
        float dy = fmaxf(fabsf(tcy - A.y) - 0.5f, 0.f);
        if (fmaf(dx, dx, dy * dy) > A.z) continue;   // warp-uniform cull

        float4 B = sB[e];                       // c00, c01, c11
        float d0 = cf - A.x;
        float m  = B.x * d0;                    // c00*d0 shared across rows

        float d1a = A.y - rf0;
        float ua  = fmaf(B.y, d1a, m);
        float ta  = fmaf(B.z * d1a, d1a, d0 * ua);
        acc0 = fmaf(A.w, ex2_fast(ta), acc0);

        float d1b = A.y - rf1;
        float ub  = fmaf(B.y, d1b, m);
        float tb  = fmaf(B.z * d1b, d1b, d0 * ub);
        acc1 = fmaf(A.w, ex2_fast(tb), acc1);
    }

    if (c < WW) {
        int base = b * (HH * WW) + c;
        if (r0 < HH)     out[base + r0 * WW]       = acc0;
        if (r0 + 1 < HH) out[base + (r0 + 1) * WW] = acc1;
    }
}

extern "C" void kernel_launch(void* const* d_in, const int* in_sizes, int n_in,
                              void* d_out, int out_size) {
    const float* stim   = (const float*)d_in[0];  // (8,225,3)
    const float* params = (const float*)d_in[1];  // (8,13)
    const float* ex     = (const float*)d_in[2];  // (1,225)
    const float* ey     = (const float*)d_in[3];  // (1,225)
    const float* slopes = (const float*)d_in[4];  // (200,200)
    // d_in[5] = pixelgrid: implied analytically, unused

    precompute_kernel<<<NB, 256>>>(stim, params, ex, ey, slopes);

    dim3 grid((WW + 31) / 32, (HH + 7) / 8, NB);   // (4,16,8)
    mvg_main_kernel<<<grid, 128>>>((float*)d_out);
}

// round 2
// speedup vs baseline: 1.5963x; 1.5963x over previous
#include <cuda_runtime.h>
#include <math.h>

// ---------------- constants matching the reference ----------------
#define HH 121
#define WW 121
#define NE 225
#define NB 8
#define NSPLIT 4
#define N_INTERP 200
#define RET_PER_DVA 280.0f
#define XRANGE0 (-15.0f)
#define YRANGE0 (-15.0f)
#define XYSTEP 0.25f
#define XLOWc (-4200.0f)
#define YLOWc (-4200.0f)
#define STEP_Xc (8400.0f/199.0f)
#define STEP_Yc (8400.0f/199.0f)
#define OD_OFF_Xc (15.5f*280.0f)
#define AMP_CUTOFF 0.25f
#define PIc 3.14159265358979323846f
#define TEMP1c (4.0f*PIc)
#define NEG_HALF_LOG2E (-0.7213475204444817f)   // -0.5*log2(e)

#define NPIX (HH*WW)

// compacted per-(b,e) table:  slot*2+0: (cx, cy2, -, bright)   slot*2+1: (c00, c01, c11, -)
__device__ float4 g_tab[NB][NE * 2];
__device__ int    g_cnt[NB];
// partial images per electrode-split
__device__ float  g_part[NSPLIT * NB * NPIX];

__global__ void precompute_kernel(const float* __restrict__ stim,
                                  const float* __restrict__ params,
                                  const float* __restrict__ elec_x,
                                  const float* __restrict__ elec_y,
                                  const float* __restrict__ slopes) {
    int b = blockIdx.x;
    const float* P = params + b * 13;
    float rho = P[0], lam = P[1], osc = P[2];
    float a0 = P[3], a1 = P[4], a2 = P[5], a3 = P[6], a4 = P[7];
    float impx = P[8], impy = P[9], rot = P[10], lodx = P[11];
    float cr = cosf(rot), sr = sinf(rot);

    int e = threadIdx.x;          // blockDim = 256, 8 warps
    bool act = false;
    float cx = 0.f, cy2 = 0.f, bright = 0.f;
    float c00 = 0.f, c01 = 0.f, c11 = 0.f;

    if (e < NE) {
        float exv = elec_x[e] * cr - elec_y[e] * sr + impx;
        float eyv = elec_x[e] * sr + elec_y[e] * cr + impy;
        float freq = stim[(b * NE + e) * 3 + 0];
        float amp  = stim[(b * NE + e) * 3 + 1];
        float pdur = stim[(b * NE + e) * 3 + 2];

        if (amp > AMP_CUTOFF) {
            act = true;
            float offx = lodx - OD_OFF_Xc;
            float qx = (exv - offx - XLOWc) / STEP_Xc;
            float qy = (eyv - YLOWc) / STEP_Yc;

            float fx = fminf(fmaxf(floorf(qx), 0.f), (float)(N_INTERP - 2));
            float fy = fminf(fmaxf(floorf(qy), 0.f), (float)(N_INTERP - 2));
            int ix = (int)fx, iy = (int)fy;
            float ax = fminf(fmaxf(qx - fx, 0.f), 1.f);
            float ay = fminf(fmaxf(qy - fy, 0.f), 1.f);
            float g00 = slopes[iy * N_INTERP + ix];
            float g01 = slopes[iy * N_INTERP + ix + 1];
            float g10 = slopes[(iy + 1) * N_INTERP + ix];
            float g11 = slopes[(iy + 1) * N_INTERP + ix + 1];
            float top = g00 + ax * (g01 - g00);
            float bot = g10 + ax * (g11 - g10);
            float th = top + ay * (bot - top);
            if (th < -PIc * 0.5f) th += PIc;
            th *= osc;

            float rs = fmaxf(rho * amp * a3, 1.0f);
            float ls = lam * powf(0.45f, -a4) * powf(pdur, a4);
            ls = fminf(fmaxf(ls, 0.f), 0.99f);
            bright = a0 * powf(fmaxf(amp, 1e-5f), a1) + a2 * freq;

            float t2 = sqrtf(1.0f - ls * ls);
            float sy = rs / (TEMP1c * t2);
            float sx = rs * t2 / TEMP1c;
            float s = sinf(th), c = cosf(th);
            float cov00 = sx * c * c + sy * s * s;
            float cov01 = (sx - sy) * s * c;
            float cov11 = sx * s * s + sy * c * c;
            float det = cov00 * cov11 - cov01 * cov01;
            float inv00 = cov11 / det;
            float inv01 = -cov01 / det;
            float inv11 = cov00 / det;

            c00 = NEG_HALF_LOG2E * inv00;
            c01 = 2.0f * NEG_HALF_LOG2E * inv01;
            c11 = NEG_HALF_LOG2E * inv11;

            cx = (exv / RET_PER_DVA - XRANGE0) / XYSTEP;
            float cy = (float)HH - (eyv / RET_PER_DVA - YRANGE0) / XYSTEP;
            cy2 = 120.0f - cy;   // d1 = cy2 - r
        }
    }

    // deterministic ballot compaction (order preserved by e)
    __shared__ int warp_cnt[8];
    unsigned mask = __ballot_sync(0xffffffffu, act);
    int lane = threadIdx.x & 31, w = threadIdx.x >> 5;
    if (lane == 0) warp_cnt[w] = __popc(mask);
    __syncthreads();
    int off = 0;
#pragma unroll
    for (int i = 0; i < 8; i++) off += (i < w) ? warp_cnt[i] : 0;
    if (threadIdx.x == 0) {
        int tot = 0;
#pragma unroll
        for (int i = 0; i < 8; i++) tot += warp_cnt[i];
        g_cnt[b] = tot;
    }
    if (act) {
        int slot = off + __popc(mask & ((1u << lane) - 1u));
        g_tab[b][slot * 2 + 0] = make_float4(cx, cy2, 0.f, bright);
        g_tab[b][slot * 2 + 1] = make_float4(c00, c01, c11, 0.f);
    }
}

__device__ __forceinline__ float ex2_fast(float x) {
    float r;
    asm("ex2.approx.ftz.f32 %0, %1;" : "=f"(r) : "f"(x));
    return r;
}

// main: grid (4, 8, NB*NSPLIT), block 128.
// warp = 32 cols x 4 rows; block = 32 cols x 16 rows. Each block handles one
// electrode chunk (split) and writes a partial image.
__global__ __launch_bounds__(128) void mvg_main_kernel() {
    __shared__ float4 sA[(NE + NSPLIT - 1) / NSPLIT + 1];
    __shared__ float4 sB[(NE + NSPLIT - 1) / NSPLIT + 1];

    int bz = blockIdx.z;
    int b = bz >> 2;          // NSPLIT == 4
    int split = bz & 3;

    int cnt = g_cnt[b];
    int chunk = (cnt + NSPLIT - 1) / NSPLIT;
    int e0 = split * chunk;
    int e1 = min(cnt, e0 + chunk);
    int len = max(e1 - e0, 0);

    for (int i = threadIdx.x; i < len; i += 128) {
        sA[i] = g_tab[b][(e0 + i) * 2 + 0];
        sB[i] = g_tab[b][(e0 + i) * 2 + 1];
    }
    __syncthreads();

    int lane = threadIdx.x & 31;
    int warp = threadIdx.x >> 5;
    int c  = blockIdx.x * 32 + lane;
    int r0 = blockIdx.y * 16 + warp * 4;

    float cf  = (float)c;
    float rf0 = (float)r0;

    float acc0 = 0.f, acc1 = 0.f, acc2 = 0.f, acc3 = 0.f;

    for (int e = 0; e < len; e++) {
        float4 A = sA[e];                        // cx, cy2, -, bright
        float4 B = sB[e];                        // c00, c01, c11
        float d0 = cf - A.x;
        float k1 = B.y * d0;                     // c01*d0
        float k0 = (B.x * d0) * d0;              // c00*d0^2

        float d1 = A.y - rf0;
        float t0 = fmaf(fmaf(B.z, d1, k1), d1, k0);
        acc0 = fmaf(A.w, ex2_fast(t0), acc0);
        d1 -= 1.0f;
        float t1 = fmaf(fmaf(B.z, d1, k1), d1, k0);
        acc1 = fmaf(A.w, ex2_fast(t1), acc1);
        d1 -= 1.0f;
        float t2 = fmaf(fmaf(B.z, d1, k1), d1, k0);
        acc2 = fmaf(A.w, ex2_fast(t2), acc2);
        d1 -= 1.0f;
        float t3 = fmaf(fmaf(B.z, d1, k1), d1, k0);
        acc3 = fmaf(A.w, ex2_fast(t3), acc3);
    }

    if (c < WW) {
        float* dst = g_part + (split * NB + b) * NPIX + c;
        if (r0 + 0 < HH) dst[(r0 + 0) * WW] = acc0;
        if (r0 + 1 < HH) dst[(r0 + 1) * WW] = acc1;
        if (r0 + 2 < HH) dst[(r0 + 2) * WW] = acc2;
        if (r0 + 3 < HH) dst[(r0 + 3) * WW] = acc3;
    }
}

// combine partials: out[b][px] = sum over splits
__global__ __launch_bounds__(256) void combine_kernel(float* __restrict__ out) {
    int i = blockIdx.x * 256 + threadIdx.x;
    if (i < NB * NPIX) {
        float v = g_part[i]
                + g_part[NB * NPIX + i]
                + g_part[2 * NB * NPIX + i]
                + g_part[3 * NB * NPIX + i];
        out[i] = v;
    }
}

extern "C" void kernel_launch(void* const* d_in, const int* in_sizes, int n_in,
                              void* d_out, int out_size) {
    const float* stim   = (const float*)d_in[0];  // (8,225,3)
    const float* params = (const float*)d_in[1];  // (8,13)
    const float* ex     = (const float*)d_in[2];  // (1,225)
    const float* ey     = (const float*)d_in[3];  // (1,225)
    const float* slopes = (const float*)d_in[4];  // (200,200)
    // d_in[5] = pixelgrid: implied analytically, unused

    precompute_kernel<<<NB, 256>>>(stim, params, ex, ey, slopes);

    dim3 grid((WW + 31) / 32, (HH + 15) / 16, NB * NSPLIT);   // (4,8,32)
    mvg_main_kernel<<<grid, 128>>>();

    combine_kernel<<<(NB * NPIX + 255) / 256, 256>>>((float*)d_out);
}

// round 3
// speedup vs baseline: 1.6174x; 1.0133x over previous
#include <cuda_runtime.h>
#include <math.h>

// ---------------- constants matching the reference ----------------
#define HH 121
#define WW 121
#define NE 225
#define NB 8
#define NSPLIT 4
#define CHUNK 57                       // ceil(225/4)
#define N_INTERP 200
#define RET_PER_DVA 280.0f
#define XRANGE0 (-15.0f)
#define YRANGE0 (-15.0f)
#define XYSTEP 0.25f
#define XLOWc (-4200.0f)
#define YLOWc (-4200.0f)
#define STEP_Xc (8400.0f/199.0f)
#define STEP_Yc (8400.0f/199.0f)
#define OD_OFF_Xc (15.5f*280.0f)
#define AMP_CUTOFF 0.25f
#define PIc 3.14159265358979323846f
#define TEMP1c (4.0f*PIc)
#define NEG_HALF_LOG2E (-0.7213475204444817f)   // -0.5*log2(e)

#define NPIX (HH*WW)

// partial images per electrode-split
__device__ float g_part[NSPLIT * NB * NPIX];

__device__ __forceinline__ float ex2_fast(float x) {
    float r;
    asm("ex2.approx.ftz.f32 %0, %1;" : "=f"(r) : "f"(x));
    return r;
}

// grid (4, 8, NB*NSPLIT), block 128.
// Phase 1: threads 0..len-1 compute per-electrode params for this block's
//          chunk (deterministic popc compaction into smem).
// Phase 2: warp = 32 cols x 4 rows tile; loop over compacted electrodes.
__global__ __launch_bounds__(128) void mvg_main_kernel(
        const float* __restrict__ stim,
        const float* __restrict__ params,
        const float* __restrict__ elec_x,
        const float* __restrict__ elec_y,
        const float* __restrict__ slopes) {
    __shared__ float4 sA[CHUNK];   // cx, cy2, -, bright
    __shared__ float4 sB[CHUNK];   // c00, c01, c11, -
    __shared__ int    wcnt[4];
    __shared__ int    s_len;

    int bz = blockIdx.z;
    int b = bz >> 2;
    int split = bz & 3;
    int e0 = split * CHUNK;
    int len = min(NE - e0, CHUNK);

    int tid = threadIdx.x;
    int lane = tid & 31, w = tid >> 5;

    // ---------------- phase 1: per-electrode precompute ----------------
    bool act = false;
    float cx = 0.f, cy2 = 0.f, bright = 0.f;
    float c00 = 0.f, c01 = 0.f, c11 = 0.f;

    if (tid < len) {
        int e = e0 + tid;
        const float* P = params + b * 13;
        float rho = P[0], lam = P[1], osc = P[2];
        float a0 = P[3], a1 = P[4], a2 = P[5], a3 = P[6], a4 = P[7];
        float impx = P[8], impy = P[9], rot = P[10], lodx = P[11];
        float cr = cosf(rot), sr = sinf(rot);

        float exv = elec_x[e] * cr - elec_y[e] * sr + impx;
        float eyv = elec_x[e] * sr + elec_y[e] * cr + impy;
        float freq = stim[(b * NE + e) * 3 + 0];
        float amp  = stim[(b * NE + e) * 3 + 1];
        float pdur = stim[(b * NE + e) * 3 + 2];

        if (amp > AMP_CUTOFF) {
            act = true;
            float offx = lodx - OD_OFF_Xc;
            float qx = (exv - offx - XLOWc) / STEP_Xc;
            float qy = (eyv - YLOWc) / STEP_Yc;

            float fx = fminf(fmaxf(floorf(qx), 0.f), (float)(N_INTERP - 2));
            float fy = fminf(fmaxf(floorf(qy), 0.f), (float)(N_INTERP - 2));
            int ix = (int)fx, iy = (int)fy;
            float ax = fminf(fmaxf(qx - fx, 0.f), 1.f);
            float ay = fminf(fmaxf(qy - fy, 0.f), 1.f);
            float g00 = slopes[iy * N_INTERP + ix];
            float g01 = slopes[iy * N_INTERP + ix + 1];
            float g10 = slopes[(iy + 1) * N_INTERP + ix];
            float g11 = slopes[(iy + 1) * N_INTERP + ix + 1];
            float top = g00 + ax * (g01 - g00);
            float bot = g10 + ax * (g11 - g10);
            float th = top + ay * (bot - top);
            if (th < -PIc * 0.5f) th += PIc;
            th *= osc;

            float rs = fmaxf(rho * amp * a3, 1.0f);
            float ls = lam * powf(0.45f, -a4) * powf(pdur, a4);
            ls = fminf(fmaxf(ls, 0.f), 0.99f);
            bright = a0 * powf(fmaxf(amp, 1e-5f), a1) + a2 * freq;

            float t2 = sqrtf(1.0f - ls * ls);
            float sy = rs / (TEMP1c * t2);
            float sx = rs * t2 / TEMP1c;
            float s = sinf(th), c = cosf(th);
            float cov00 = sx * c * c + sy * s * s;
            float cov01 = (sx - sy) * s * c;
            float cov11 = sx * s * s + sy * c * c;
            float det = cov00 * cov11 - cov01 * cov01;
            float inv00 = cov11 / det;
            float inv01 = -cov01 / det;
            float inv11 = cov00 / det;

            c00 = NEG_HALF_LOG2E * inv00;
            c01 = 2.0f * NEG_HALF_LOG2E * inv01;
            c11 = NEG_HALF_LOG2E * inv11;

            cx = (exv / RET_PER_DVA - XRANGE0) / XYSTEP;
            float cy = (float)HH - (eyv / RET_PER_DVA - YRANGE0) / XYSTEP;
            cy2 = 120.0f - cy;   // d1 = cy2 - r
        }
    }

    // deterministic popc compaction (ascending e preserved)
    unsigned mask = __ballot_sync(0xffffffffu, act);
    if (lane == 0) wcnt[w] = __popc(mask);
    __syncthreads();
    int off = 0;
#pragma unroll
    for (int i = 0; i < 4; i++) off += (i < w) ? wcnt[i] : 0;
    if (tid == 0) s_len = wcnt[0] + wcnt[1] + wcnt[2] + wcnt[3];
    if (act) {
        int slot = off + __popc(mask & ((1u << lane) - 1u));
        sA[slot] = make_float4(cx, cy2, 0.f, bright);
        sB[slot] = make_float4(c00, c01, c11, 0.f);
    }
    __syncthreads();
    int n = s_len;

    // ---------------- phase 2: pixel loop ----------------
    int c  = blockIdx.x * 32 + lane;
    int r0 = blockIdx.y * 16 + w * 4;

    float cf  = (float)c;
    float rf0 = (float)r0;

    float acc0 = 0.f, acc1 = 0.f, acc2 = 0.f, acc3 = 0.f;

    for (int e = 0; e < n; e++) {
        float4 A = sA[e];
        float4 B = sB[e];
        float d0 = cf - A.x;
        float k1 = B.y * d0;                     // c01*d0
        float k0 = (B.x * d0) * d0;              // c00*d0^2

        float d1 = A.y - rf0;
        float t0 = fmaf(fmaf(B.z, d1, k1), d1, k0);
        acc0 = fmaf(A.w, ex2_fast(t0), acc0);
        d1 -= 1.0f;
        float t1 = fmaf(fmaf(B.z, d1, k1), d1, k0);
        acc1 = fmaf(A.w, ex2_fast(t1), acc1);
        d1 -= 1.0f;
        float t2 = fmaf(fmaf(B.z, d1, k1), d1, k0);
        acc2 = fmaf(A.w, ex2_fast(t2), acc2);
        d1 -= 1.0f;
        float t3 = fmaf(fmaf(B.z, d1, k1), d1, k0);
        acc3 = fmaf(A.w, ex2_fast(t3), acc3);
    }

    if (c < WW) {
        float* dst = g_part + (split * NB + b) * NPIX + c;
        if (r0 + 0 < HH) dst[(r0 + 0) * WW] = acc0;
        if (r0 + 1 < HH) dst[(r0 + 1) * WW] = acc1;
        if (r0 + 2 < HH) dst[(r0 + 2) * WW] = acc2;
        if (r0 + 3 < HH) dst[(r0 + 3) * WW] = acc3;
    }
}

// combine partials (float4: NB*NPIX = 117128 divisible by 4; split stride too)
#define NQ ((NB * NPIX) / 4)
__global__ __launch_bounds__(256) void combine_kernel(float4* __restrict__ out) {
    int i = blockIdx.x * 256 + threadIdx.x;
    if (i < NQ) {
        const float4* p = (const float4*)g_part;
        float4 v0 = p[i];
        float4 v1 = p[NQ + i];
        float4 v2 = p[2 * NQ + i];
        float4 v3 = p[3 * NQ + i];
        float4 r;
        r.x = v0.x + v1.x + v2.x + v3.x;
        r.y = v0.y + v1.y + v2.y + v3.y;
        r.z = v0.z + v1.z + v2.z + v3.z;
        r.w = v0.w + v1.w + v2.w + v3.w;
        out[i] = r;
    }
}

extern "C" void kernel_launch(void* const* d_in, const int* in_sizes, int n_in,
                              void* d_out, int out_size) {
    const float* stim   = (const float*)d_in[0];  // (8,225,3)
    const float* params = (const float*)d_in[1];  // (8,13)
    const float* ex     = (const float*)d_in[2];  // (1,225)
    const float* ey     = (const float*)d_in[3];  // (1,225)
    const float* slopes = (const float*)d_in[4];  // (200,200)
    // d_in[5] = pixelgrid: implied analytically, unused

    dim3 grid((WW + 31) / 32, (HH + 15) / 16, NB * NSPLIT);   // (4,8,32)
    mvg_main_kernel<<<grid, 128>>>(stim, params, ex, ey, slopes);

    combine_kernel<<<(NQ + 255) / 256, 256>>>((float4*)d_out);
}

// round 4
// speedup vs baseline: 1.8405x; 1.1379x over previous
#include <cuda_runtime.h>
#include <math.h>

// ---------------- constants matching the reference ----------------
#define HH 121
#define WW 121
#define NE 225
#define NB 8
#define NSPLIT 4
#define CHUNK 57                       // ceil(225/4)
#define N_INTERP 200
#define RET_PER_DVA 280.0f
#define XRANGE0 (-15.0f)
#define YRANGE0 (-15.0f)
#define XYSTEP 0.25f
#define XLOWc (-4200.0f)
#define YLOWc (-4200.0f)
#define STEP_Xc (8400.0f/199.0f)
#define STEP_Yc (8400.0f/199.0f)
#define OD_OFF_Xc (15.5f*280.0f)
#define AMP_CUTOFF 0.25f
#define PIc 3.14159265358979323846f
#define TEMP1c (4.0f*PIc)
#define NEG_HALF_LOG2E (-0.7213475204444817f)   // -0.5*log2(e)
#define LOG2_045 (-1.1520030934450498f)         // log2(0.45)

#define NPIX (HH*WW)
#define TILES_X 4
#define TILES_Y 8

// partial images per electrode-split
__device__ float g_part[NSPLIT * NB * NPIX];
// per-(b, tile) completion counters (statically zero; reset by finisher)
__device__ int   g_done[NB * TILES_X * TILES_Y];

__device__ __forceinline__ float ex2_fast(float x) {
    float r;
    asm("ex2.approx.ftz.f32 %0, %1;" : "=f"(r) : "f"(x));
    return r;
}

// grid (4, 8, NB*NSPLIT), block 128.
// Phase 1: per-electrode params for this block's chunk (popc compaction).
// Phase 2: warp = 32 cols x 4 rows tile; loop over compacted electrodes.
// Phase 3: last split-block for this (b,tile) sums partials -> out.
__global__ __launch_bounds__(128) void mvg_main_kernel(
        const float* __restrict__ stim,
        const float* __restrict__ params,
        const float* __restrict__ elec_x,
        const float* __restrict__ elec_y,
        const float* __restrict__ slopes,
        float* __restrict__ out) {
    __shared__ float4 sA[CHUNK];   // cx, cy2, -, bright
    __shared__ float4 sB[CHUNK];   // c00, c01, c11, -
    __shared__ int    wcnt[4];
    __shared__ int    s_len;
    __shared__ int    s_last;

    int bz = blockIdx.z;
    int b = bz >> 2;
    int split = bz & 3;
    int e0 = split * CHUNK;
    int len = min(NE - e0, CHUNK);

    int tid = threadIdx.x;
    int lane = tid & 31, w = tid >> 5;

    // ---------------- phase 1: per-electrode precompute ----------------
    bool act = false;
    float cx = 0.f, cy2 = 0.f, bright = 0.f;
    float c00 = 0.f, c01 = 0.f, c11 = 0.f;

    if (tid < len) {
        int e = e0 + tid;
        const float* P = params + b * 13;
        float rho = P[0], lam = P[1], osc = P[2];
        float a0 = P[3], a1 = P[4], a2 = P[5], a3 = P[6], a4 = P[7];
        float impx = P[8], impy = P[9], rot = P[10], lodx = P[11];
        float cr = __cosf(rot), sr = __sinf(rot);

        float exv = elec_x[e] * cr - elec_y[e] * sr + impx;
        float eyv = elec_x[e] * sr + elec_y[e] * cr + impy;
        float freq = stim[(b * NE + e) * 3 + 0];
        float amp  = stim[(b * NE + e) * 3 + 1];
        float pdur = stim[(b * NE + e) * 3 + 2];

        if (amp > AMP_CUTOFF) {
            act = true;
            float offx = lodx - OD_OFF_Xc;
            float qx = (exv - offx - XLOWc) * (1.0f / STEP_Xc);
            float qy = (eyv - YLOWc) * (1.0f / STEP_Yc);

            float fx = fminf(fmaxf(floorf(qx), 0.f), (float)(N_INTERP - 2));
            float fy = fminf(fmaxf(floorf(qy), 0.f), (float)(N_INTERP - 2));
            int ix = (int)fx, iy = (int)fy;
            float ax = fminf(fmaxf(qx - fx, 0.f), 1.f);
            float ay = fminf(fmaxf(qy - fy, 0.f), 1.f);
            float g00 = slopes[iy * N_INTERP + ix];
            float g01 = slopes[iy * N_INTERP + ix + 1];
            float g10 = slopes[(iy + 1) * N_INTERP + ix];
            float g11 = slopes[(iy + 1) * N_INTERP + ix + 1];
            float top = g00 + ax * (g01 - g00);
            float bot = g10 + ax * (g11 - g10);
            float th = top + ay * (bot - top);
            if (th < -PIc * 0.5f) th += PIc;
            th *= osc;

            float rs = fmaxf(rho * amp * a3, 1.0f);
            // 0.45^-a4 * pdur^a4 = exp2(a4*(log2(pdur) - log2(0.45)))
            float ls = lam * ex2_fast(a4 * (__log2f(pdur) - LOG2_045));
            ls = fminf(fmaxf(ls, 0.f), 0.99f);
            // amp^a1 = exp2(a1*log2(amp)); amp > 0.25 here
            bright = a0 * ex2_fast(a1 * __log2f(fmaxf(amp, 1e-5f))) + a2 * freq;

            float t2 = sqrtf(1.0f - ls * ls);
            float sy = __fdividef(rs, TEMP1c * t2);
            float sx = rs * t2 * (1.0f / TEMP1c);
            float s = __sinf(th), c = __cosf(th);
            float cov00 = sx * c * c + sy * s * s;
            float cov01 = (sx - sy) * s * c;
            float cov11 = sx * s * s + sy * c * c;
            float det = cov00 * cov11 - cov01 * cov01;
            float rdet = __fdividef(1.0f, det);
            float inv00 = cov11 * rdet;
            float inv01 = -cov01 * rdet;
            float inv11 = cov00 * rdet;

            c00 = NEG_HALF_LOG2E * inv00;
            c01 = 2.0f * NEG_HALF_LOG2E * inv01;
            c11 = NEG_HALF_LOG2E * inv11;

            cx = (exv / RET_PER_DVA - XRANGE0) / XYSTEP;
            float cy = (float)HH - (eyv / RET_PER_DVA - YRANGE0) / XYSTEP;
            cy2 = 120.0f - cy;   // d1 = cy2 - r
        }
    }

    // deterministic popc compaction (ascending e preserved)
    unsigned mask = __ballot_sync(0xffffffffu, act);
    if (lane == 0) wcnt[w] = __popc(mask);
    __syncthreads();
    int off = 0;
#pragma unroll
    for (int i = 0; i < 4; i++) off += (i < w) ? wcnt[i] : 0;
    if (tid == 0) s_len = wcnt[0] + wcnt[1] + wcnt[2] + wcnt[3];
    if (act) {
        int slot = off + __popc(mask & ((1u << lane) - 1u));
        sA[slot] = make_float4(cx, cy2, 0.f, bright);
        sB[slot] = make_float4(c00, c01, c11, 0.f);
    }
    __syncthreads();
    int n = s_len;

    // ---------------- phase 2: pixel loop ----------------
    int c  = blockIdx.x * 32 + lane;
    int r0 = blockIdx.y * 16 + w * 4;

    float cf  = (float)c;
    float rf0 = (float)r0;

    float acc0 = 0.f, acc1 = 0.f, acc2 = 0.f, acc3 = 0.f;

    for (int e = 0; e < n; e++) {
        float4 A = sA[e];
        float4 B = sB[e];
        float d0 = cf - A.x;
        float k1 = B.y * d0;                     // c01*d0
        float k0 = (B.x * d0) * d0;              // c00*d0^2

        float d1 = A.y - rf0;
        float t0 = fmaf(fmaf(B.z, d1, k1), d1, k0);
        acc0 = fmaf(A.w, ex2_fast(t0), acc0);
        d1 -= 1.0f;
        float t1 = fmaf(fmaf(B.z, d1, k1), d1, k0);
        acc1 = fmaf(A.w, ex2_fast(t1), acc1);
        d1 -= 1.0f;
        float t2 = fmaf(fmaf(B.z, d1, k1), d1, k0);
        acc2 = fmaf(A.w, ex2_fast(t2), acc2);
        d1 -= 1.0f;
        float t3 = fmaf(fmaf(B.z, d1, k1), d1, k0);
        acc3 = fmaf(A.w, ex2_fast(t3), acc3);
    }

    float* dst = g_part + (split * NB + b) * NPIX + c;
    if (c < WW) {
        if (r0 + 0 < HH) dst[(r0 + 0) * WW] = acc0;
        if (r0 + 1 < HH) dst[(r0 + 1) * WW] = acc1;
        if (r0 + 2 < HH) dst[(r0 + 2) * WW] = acc2;
        if (r0 + 3 < HH) dst[(r0 + 3) * WW] = acc3;
    }

    // ---------------- phase 3: last-block reduction ----------------
    __threadfence();
    __syncthreads();
    if (tid == 0) {
        int idx = (b * TILES_X + blockIdx.x) * TILES_Y + blockIdx.y;
        int old = atomicAdd(&g_done[idx], 1);
        s_last = (old == NSPLIT - 1) ? 1 : 0;
        if (s_last) g_done[idx] = 0;      // reset for next graph replay
    }
    __syncthreads();

    if (s_last) {
        int col0 = blockIdx.x * 32;
        int row0 = blockIdx.y * 16;
        for (int k = tid; k < 512; k += 128) {
            int r = row0 + (k >> 5);
            int cc = col0 + (k & 31);
            if (r < HH && cc < WW) {
                int p = r * WW + cc;
                // fixed split order -> deterministic fp sum
                float v = __ldcg(&g_part[(0 * NB + b) * NPIX + p])
                        + __ldcg(&g_part[(1 * NB + b) * NPIX + p])
                        + __ldcg(&g_part[(2 * NB + b) * NPIX + p])
                        + __ldcg(&g_part[(3 * NB + b) * NPIX + p]);
                out[b * NPIX + p] = v;
            }
        }
    }
}

extern "C" void kernel_launch(void* const* d_in, const int* in_sizes, int n_in,
                              void* d_out, int out_size) {
    const float* stim   = (const float*)d_in[0];  // (8,225,3)
    const float* params = (const float*)d_in[1];  // (8,13)
    const float* ex     = (const float*)d_in[2];  // (1,225)
    const float* ey     = (const float*)d_in[3];  // (1,225)
    const float* slopes = (const float*)d_in[4];  // (200,200)
    // d_in[5] = pixelgrid: implied analytically, unused

    dim3 grid(TILES_X, TILES_Y, NB * NSPLIT);   // (4,8,32)
    mvg_main_kernel<<<grid, 128>>>(stim, params, ex, ey, slopes, (float*)d_out);
}